// round 16
// baseline (speedup 1.0000x reference)
#include <cuda_runtime.h>
#include <math.h>

// Per-batch params: [0..63]=cos(angle), [64..127]=sin(angle), [128..191]=amplitude
__device__ float g_params[192];

// Channel-mean dmap (fallback path only): N*DH*DW floats.
#define DMEAN_CAP (1 << 21)
__device__ float g_dmean[DMEAN_CAP];

// x-upsampled (x-lerped) mean dmap at full width: [N][DH][W].
#define DX_CAP (1 << 23)
__device__ float g_dx[DX_CAP];

// ---- Fused prepass: per-row channel-mean (smem) + x-upsample + params ----
// Grid: (DH, N). Requires DW <= 1024 and (DW*DC)%4 == 0 (16B-aligned rows).
__global__ void __launch_bounds__(256) fused_prep_kernel(
        const float* __restrict__ dmap,
        const float* __restrict__ amp,
        const float* __restrict__ ang,
        int W, int DH, int DW, int DC, int N, float scx) {
    __shared__ float s_mean[1024];
    int dh = blockIdx.x;
    int n  = blockIdx.y;
    int tid = threadIdx.x;

    if (dh == 0 && n == 0 && tid < (unsigned)N) {
        float a = ang[tid];
        g_params[tid]       = cosf(a);
        g_params[64 + tid]  = sinf(a);
        g_params[128 + tid] = amp[tid];
    }

    // Phase 1: channel-mean of this dmap row into smem.
    const float* row = dmap + (size_t)(n * DH + dh) * DW * DC;
    if (DC == 3) {
        int groups = DW >> 2;       // 4 pixels = 3 float4s per group
        for (int g = tid; g < groups; g += 256) {
            const float4* p = (const float4*)(row + g * 12);
            float4 a = __ldg(p), b = __ldg(p + 1), c = __ldg(p + 2);
            const float k = 1.0f / 3.0f;
            int o = g * 4;
            s_mean[o + 0] = (a.x + a.y + a.z) * k;
            s_mean[o + 1] = (a.w + b.x + b.y) * k;
            s_mean[o + 2] = (b.z + b.w + c.x) * k;
            s_mean[o + 3] = (c.y + c.z + c.w) * k;
        }
        for (int p = (groups << 2) + tid; p < DW; p += 256)
            s_mean[p] = (row[p*3] + row[p*3+1] + row[p*3+2]) * (1.0f / 3.0f);
    } else {
        for (int p = tid; p < DW; p += 256)
            s_mean[p] = row[p];
    }
    __syncthreads();

    // Phase 2: x-lerp to width W, float4 stores.
    float* orow = g_dx + (size_t)(n * DH + dh) * W;
    for (int X0 = tid * 4; X0 < W; X0 += 1024) {
        if (X0 + 4 <= W) {
            float4 v;
            float* vp = (float*)&v;
            #pragma unroll
            for (int j = 0; j < 4; j++) {
                int X = X0 + j;
                float sx = fmaf((float)X + 0.5f, scx, -0.5f);
                float fx0 = floorf(sx);
                float wx = sx - fx0;
                int f = (int)fx0;
                int dx0 = min(max(f, 0), DW - 1);
                int dx1 = min(max(f + 1, 0), DW - 1);
                float t0 = s_mean[dx0], t1 = s_mean[dx1];
                vp[j] = t0 + (t1 - t0) * wx;
            }
            *(float4*)(orow + X0) = v;
        } else {
            for (int X = X0; X < W; X++) {
                float sx = fmaf((float)X + 0.5f, scx, -0.5f);
                float fx0 = floorf(sx);
                float wx = sx - fx0;
                int f = (int)fx0;
                int dx0 = min(max(f, 0), DW - 1);
                int dx1 = min(max(f + 1, 0), DW - 1);
                float t0 = s_mean[dx0], t1 = s_mean[dx1];
                orow[X] = t0 + (t1 - t0) * wx;
            }
        }
    }
}

// ---- Fallback prepass (generic shapes): mean then xup ----
__global__ void __launch_bounds__(256) mean_kernel(
        const float* __restrict__ dmap,
        const float* __restrict__ amp,
        const float* __restrict__ ang,
        int total, int DC, int N) {
    if (blockIdx.x == 0 && threadIdx.x < (unsigned)N) {
        float a = ang[threadIdx.x];
        g_params[threadIdx.x]       = cosf(a);
        g_params[64 + threadIdx.x]  = sinf(a);
        g_params[128 + threadIdx.x] = amp[threadIdx.x];
    }
    int t = blockIdx.x * blockDim.x + threadIdx.x;
    if (t >= total) return;
    if (DC == 3)
        g_dmean[t] = (dmap[t*3] + dmap[t*3+1] + dmap[t*3+2]) * (1.0f / 3.0f);
    else
        g_dmean[t] = dmap[t];
}

__global__ void __launch_bounds__(256) xup_kernel(
        int W, int DH, int DW, float scx) {
    int X  = blockIdx.x * blockDim.x + threadIdx.x;
    int dh = blockIdx.y;
    int n  = blockIdx.z;
    if (X >= W) return;
    float sx = fmaf((float)X + 0.5f, scx, -0.5f);
    float fx0 = floorf(sx);
    float wx = sx - fx0;
    int f = (int)fx0;
    int dx0 = min(max(f, 0), DW - 1);
    int dx1 = min(max(f + 1, 0), DW - 1);
    const float* row = g_dmean + (n * DH + dh) * DW;
    float t0 = __ldg(row + dx0);
    float t1 = __ldg(row + dx1);
    g_dx[(n * DH + dh) * W + X] = t0 + (t1 - t0) * wx;
}

// Branchless reflection (align_corners=False), exact over the reachable range.
__device__ __forceinline__ float reflect_small(float v, float size) {
    v = fabsf(v + 0.5f) - 0.5f;
    float e = size - 0.5f;
    v = e - fabsf(v - e);
    return fminf(fmaxf(v, 0.0f), size - 1.0f);
}

// One pixel of the displace: dmap y-lerp, position, reflect, gather.
__device__ __forceinline__ void displace_px(
        const float* __restrict__ img,
        int x, int y, int n, int H, int W, int DH, int W3,
        float scy, float fwx, float fwy, int totalFloats,
        float cth, float sth, float amp, const float* __restrict__ dxcol,
        float& o0, float& o1, float& o2) {
    // dmap y-lerp (x-lerp precomputed; dxcol = g_dx + n*DH*W + x)
    float sy = fmaf((float)y + 0.5f, scy, -0.5f);
    float fy0 = floorf(sy);
    float wy = sy - fy0;
    int fy = (int)fy0;
    int dy0 = min(max(fy, 0), DH - 1);
    int dy1 = min(max(fy + 1, 0), DH - 1);
    float m0 = __ldg(dxcol + dy0 * W);
    float m1 = __ldg(dxcol + dy1 * W);
    float dm = m0 + (m1 - m0) * wy;

    // sampling position
    float d = dm * amp;
    float ix = fmaf((float)x + cth * d, fwx, -0.5f);
    float iy = fmaf((float)y + sth * d, fwy, -0.5f);
    ix = reflect_small(ix, (float)W);
    iy = reflect_small(iy, (float)H);

    float px0 = floorf(ix), py0 = floorf(iy);
    float bx = ix - px0, by = iy - py0;
    int ix0 = (int)px0;
    int iy0 = (int)py0;
    int iy1 = min(iy0 + 1, H - 1);

    // gather: wide tap-row loads, single bounds check
    int nOff = n * H * W3;
    int off  = 3 * ix0;
    int offe = off & ~1;
    int s    = off & 1;
    int idxA = nOff + iy0 * W3 + offe;
    int idxB = nOff + iy1 * W3 + offe;

    float a0, a1, a2, a3, a4, a5;
    float b0, b1, b2, b3, b4, b5;
    if (idxB + 8 <= totalFloats) {
        const float2* pA = (const float2*)(img + idxA);
        const float2* pB = (const float2*)(img + idxB);
        float2 A0 = __ldg(pA), A1 = __ldg(pA + 1), A2 = __ldg(pA + 2), A3 = __ldg(pA + 3);
        float2 B0 = __ldg(pB), B1 = __ldg(pB + 1), B2 = __ldg(pB + 2), B3 = __ldg(pB + 3);
        a0 = s ? A0.y : A0.x;  a1 = s ? A1.x : A0.y;  a2 = s ? A1.y : A1.x;
        a3 = s ? A2.x : A1.y;  a4 = s ? A2.y : A2.x;  a5 = s ? A3.x : A2.y;
        b0 = s ? B0.y : B0.x;  b1 = s ? B1.x : B0.y;  b2 = s ? B1.y : B1.x;
        b3 = s ? B2.x : B1.y;  b4 = s ? B2.y : B2.x;  b5 = s ? B3.x : B2.y;
        // At ix0 == W-1 the second tap has weight bx == 0, so the values it
        // reads (next row) never affect the output.
    } else {
        int ix1 = min(ix0 + 1, W - 1);
        const float* pa = img + nOff + iy0 * W3 + 3 * ix0;
        const float* pc = img + nOff + iy0 * W3 + 3 * ix1;
        const float* pb = img + nOff + iy1 * W3 + 3 * ix0;
        const float* pd = img + nOff + iy1 * W3 + 3 * ix1;
        a0 = __ldg(pa); a1 = __ldg(pa + 1); a2 = __ldg(pa + 2);
        a3 = __ldg(pc); a4 = __ldg(pc + 1); a5 = __ldg(pc + 2);
        b0 = __ldg(pb); b1 = __ldg(pb + 1); b2 = __ldg(pb + 2);
        b3 = __ldg(pd); b4 = __ldg(pd + 1); b5 = __ldg(pd + 2);
    }

    float w00 = (1.0f - bx) * (1.0f - by);
    float w01 = bx * (1.0f - by);
    float w10 = (1.0f - bx) * by;
    float w11 = bx * by;

    o0 = w00 * a0 + w01 * a3 + w10 * b0 + w11 * b3;
    o1 = w00 * a1 + w01 * a4 + w10 * b1 + w11 * b4;
    o2 = w00 * a2 + w01 * a5 + w10 * b2 + w11 * b5;
}

// ---- Displace: 2 pixels/thread split in y + smem-staged float4 stores ----
__global__ void __launch_bounds__(256) displace_kernel(
        const float* __restrict__ img,
        float* __restrict__ out,
        int H, int W, int DH, int W3, int halfH,
        float scy, float fwx, float fwy, int totalFloats) {
    __shared__ __align__(16) float s_out[2 * 768];   // 2 rows x 256 px x 3ch

    int t  = threadIdx.x;
    int x  = blockIdx.x * blockDim.x + t;
    int y0 = blockIdx.y;
    int n  = blockIdx.z;

    bool valid = (x < W);
    int xc = valid ? x : (W - 1);       // clamp for compute; stores predicated
    int y1 = y0 + halfH;
    bool hasY1 = (y1 < H);

    float cth = __ldg(&g_params[n]);
    float sth = __ldg(&g_params[64 + n]);
    float amp = __ldg(&g_params[128 + n]);
    const float* dxcol = g_dx + n * DH * W + xc;

    float p0, p1, p2, q0 = 0.f, q1 = 0.f, q2 = 0.f;
    displace_px(img, xc, y0, n, H, W, DH, W3,
                scy, fwx, fwy, totalFloats, cth, sth, amp, dxcol, p0, p1, p2);
    if (hasY1)
        displace_px(img, xc, y1, n, H, W, DH, W3,
                    scy, fwx, fwy, totalFloats, cth, sth, amp, dxcol, q0, q1, q2);

    int blockStart = blockIdx.x * blockDim.x;
    bool fastBlock = (blockStart + 256 <= W);   // full-width block

    if (fastBlock) {
        s_out[t * 3 + 0] = p0;
        s_out[t * 3 + 1] = p1;
        s_out[t * 3 + 2] = p2;
        s_out[768 + t * 3 + 0] = q0;
        s_out[768 + t * 3 + 1] = q1;
        s_out[768 + t * 3 + 2] = q2;
        __syncthreads();
        // 192 float4s per row; row bases are 16B-aligned (blockStart*3 % 4 == 0).
        float4* r0 = (float4*)(out + (size_t)(n * H + y0) * W3 + blockStart * 3);
        if (t < 192)
            r0[t] = *(const float4*)(s_out + t * 4);
        if (hasY1) {
            float4* r1 = (float4*)(out + (size_t)(n * H + y1) * W3 + blockStart * 3);
            int t2 = t - 64;
            if (t2 >= 0)
                r1[t2] = *(const float4*)(s_out + 768 + t2 * 4);
        }
    } else if (valid) {
        int ob0 = (n * H + y0) * W3 + 3 * x;
        out[ob0 + 0] = p0; out[ob0 + 1] = p1; out[ob0 + 2] = p2;
        if (hasY1) {
            int ob1 = (n * H + y1) * W3 + 3 * x;
            out[ob1 + 0] = q0; out[ob1 + 1] = q1; out[ob1 + 2] = q2;
        }
    }
}

extern "C" void kernel_launch(void* const* d_in, const int* in_sizes, int n_in,
                              void* d_out, int out_size) {
    const float* img  = (const float*)d_in[0];
    const float* dmap = (const float*)d_in[1];
    const float* amp  = (const float*)d_in[2];
    const float* ang  = (const float*)d_in[3];
    float* out = (float*)d_out;

    int N = in_sizes[2];
    long long ipix = (long long)in_sizes[0] / ((long long)N * 3);
    int H = (int)(sqrt((double)ipix) + 0.5);
    int W = H;

    int DC = 3;
    long long dpix = (long long)in_sizes[1] / ((long long)N * 3);
    int DH = (int)(sqrt((double)dpix) + 0.5);
    if ((long long)DH * DH != dpix) {
        DC = 1;
        dpix = (long long)in_sizes[1] / N;
        DH = (int)(sqrt((double)dpix) + 0.5);
    }
    int DW = DH;

    float scx = (float)DW / (float)W;

    if (DW <= 1024 && ((DW * DC) % 4 == 0) && (DC == 1 || DC == 3)) {
        dim3 fgrid(DH, N);
        fused_prep_kernel<<<fgrid, 256>>>(dmap, amp, ang, W, DH, DW, DC, N, scx);
    } else {
        int total = N * DH * DW;
        mean_kernel<<<(total + 255) / 256, 256>>>(dmap, amp, ang, total, DC, N);
        dim3 xgrid((W + 255) / 256, DH, N);
        xup_kernel<<<xgrid, 256>>>(W, DH, DW, scx);
    }

    float scy = (float)DH / (float)H;
    float fwx = (float)W / (float)(W - 1);
    float fwy = (float)H / (float)(H - 1);
    int W3 = W * 3;
    int totalFloats = N * H * W3;
    int halfH = (H + 1) / 2;
    dim3 grid((W + 255) / 256, halfH, N);
    displace_kernel<<<grid, 256>>>(img, out, H, W, DH, W3, halfH,
                                   scy, fwx, fwy, totalFloats);
}